// round 14
// baseline (speedup 1.0000x reference)
#include <cuda_runtime.h>
#include <cuda_fp16.h>
#include <cstdint>

// Problem constants
#define BB 16
#define CC 256
#define HWS 4096
#define NPIX 65536
#define DD 2048
#define MOM 0.99f
#define OMM 0.01f
#define EPSV 1e-5f

// Output layout (float32, reference return order)
#define OFF_Q    0
#define OFF_LOSS 16777216
#define OFF_IDS  16777217
#define OFF_NE   16842753
#define OFF_NCS  17367041
#define OFF_NEA  17369089

#define NKC 16            // K chunks of 16 (K=256)
#define NTP 8             // N-tile pairs (2048 codes / 256)
#define NIT (NTP * NKC)   // 128 mainloop iterations
#define NSTG 3            // cp.async pipeline stages
#define TAU 0.15f         // screen ambiguity threshold (see error analysis)

// Dynamic smem for k_screen (per CTA = 57344 B -> 2 CTAs/SM)
#define APL_OFF 0         // A hi plane: [kc 16][oct 2][px 64] x 16B = 32768
#define BST_OFF 32768     // B stages: 3 x 8192 = 24576
#define SMEM_DYN 57344

// Scratch (small device globals only)
__device__ __align__(16) unsigned char g_Bpl[16u*NKC*4096u]; // [ntile][kchunk] 4KB fp16 HI embed plane
__device__ float g_embed_norm[DD];
__device__ int   g_ids[NPIX];
__device__ float g_counts[DD];
__device__ float g_embed_sum[CC * DD];
__device__ float g_inv_cs[DD];
__device__ float g_sse;
__device__ int   g_nfix;
__device__ int   g_fix[NPIX];

// ---------------- PTX helpers (sm_80-baseline features only) ----------------
__device__ __forceinline__ uint32_t smem_u32(const void* p) {
    uint32_t a;
    asm("{ .reg .u64 t; cvta.to.shared.u64 t, %1; cvt.u32.u64 %0, t; }" : "=r"(a) : "l"(p));
    return a;
}
#define CP16(dst, src) asm volatile("cp.async.cg.shared.global [%0], [%1], 16;" :: "r"(dst), "l"(src))
#define CP_COMMIT() asm volatile("cp.async.commit_group;" ::: "memory")
#define CP_WAIT1()  asm volatile("cp.async.wait_group 1;" ::: "memory")
#define CP_WAIT0()  asm volatile("cp.async.wait_group 0;" ::: "memory")

#define LDSM_X4(r0,r1,r2,r3,addr) \
    asm volatile("ldmatrix.sync.aligned.m8n8.x4.shared.b16 {%0,%1,%2,%3}, [%4];" \
        : "=r"(r0),"=r"(r1),"=r"(r2),"=r"(r3) : "r"(addr))
#define LDSM_X4_T(r0,r1,r2,r3,addr) \
    asm volatile("ldmatrix.sync.aligned.m8n8.x4.trans.shared.b16 {%0,%1,%2,%3}, [%4];" \
        : "=r"(r0),"=r"(r1),"=r"(r2),"=r"(r3) : "r"(addr))

#define MMA16816(c, a0,a1,a2,a3, b0,b1) \
    asm volatile("mma.sync.aligned.m16n8k16.row.col.f32.f16.f16.f32 " \
        "{%0,%1,%2,%3}, {%4,%5,%6,%7}, {%8,%9}, {%0,%1,%2,%3};" \
        : "+f"((c)[0]),"+f"((c)[1]),"+f"((c)[2]),"+f"((c)[3]) \
        : "r"(a0),"r"(a1),"r"(a2),"r"(a3),"r"(b0),"r"(b1))

// ---------------------------------------------------------------------------
__global__ void k_zero() {
    int idx = blockIdx.x * 256 + threadIdx.x;
    if (idx < CC * DD)                 g_embed_sum[idx] = 0.f;
    else if (idx < CC * DD + DD)       g_counts[idx - CC * DD] = 0.f;
    else if (idx == CC * DD + DD)      g_sse = 0.f;
    else if (idx == CC * DD + DD + 1)  g_nfix = 0;
}

__global__ void k_norm(const float* __restrict__ embed) {
    int warp = threadIdx.x >> 5, lane = threadIdx.x & 31;
    int d = blockIdx.x * 8 + warp;
    const float* row = embed + d * CC;
    float s = 0.f;
#pragma unroll
    for (int j = 0; j < 8; j++) { float v = row[lane + 32 * j]; s = fmaf(v, v, s); }
#pragma unroll
    for (int o = 16; o; o >>= 1) s += __shfl_xor_sync(0xffffffffu, s, o);
    if (lane == 0) g_embed_norm[d] = s;
}

// ---------------------------------------------------------------------------
// prep_B: embed -> fp16 HI plane only. Chunk (nt,kc) = 4KB:
// [k 16][swizzled 16B unit = 8 consecutive n]; swz conflict-free for ldsm.trans
// ---------------------------------------------------------------------------
__global__ __launch_bounds__(256) void prep_B(const float* __restrict__ embed) {
    const int nt = blockIdx.x / NKC, kc = blockIdx.x % NKC;
    const int t = threadIdx.x;
    const int k = t >> 4, nblk = t & 15;
    const int kglob = kc * 16 + k;
    const int n0 = nt * 128 + nblk * 8;
    uint32_t hu[4];
#pragma unroll
    for (int nn = 0; nn < 8; nn += 2) {
        __half h0 = __float2half_rn(embed[(n0 + nn) * CC + kglob]);
        __half h1 = __float2half_rn(embed[(n0 + nn + 1) * CC + kglob]);
        hu[nn >> 1] = (uint32_t)__half_as_ushort(h0) | ((uint32_t)__half_as_ushort(h1) << 16);
    }
    const int swz = (nblk & 8) | ((nblk ^ (k & 7)) & 7);
    unsigned char* ob = g_Bpl + ((size_t)(nt * NKC + kc) << 12);
    *(uint4*)(ob + k * 256 + swz * 16) = *(uint4*)hu;
}

// ---------------------------------------------------------------------------
// k_screen: fp16-hi mma.sync screening GEMM + top-2 argmax.
// screened score = (2x)_h . e_h - |e|^2 ; err ~1.3e-2 rms << typical gaps.
// Pixels with (best - second) < TAU appended to g_fix for exact rescore.
// CTA = 64 pixels, 2 CTAs/SM, 3-stage cp.async, 1 barrier/iter (R10 skeleton).
// 8 warps as 2M x 4N; warp tile 32px x 64 codes.
// ---------------------------------------------------------------------------
__global__ __launch_bounds__(256, 2) void k_screen(const float* __restrict__ x,
                                                   float* __restrict__ out_ids) {
    extern __shared__ __align__(16) unsigned char smdyn[];
    const uint32_t sbase = smem_u32(smdyn);
    const uint32_t APL = sbase + APL_OFF;
    const uint32_t BST = sbase + BST_OFF;
    const int tid = threadIdx.x;
    const int lane = tid & 31, wid = tid >> 5;
    const int wm0 = (wid >> 2) * 32;     // warp pixel base
    const int ncol = wid & 3;
    const int wn0 = ncol * 64;           // warp code base within the 256-code stage
    const int mblk = blockIdx.x;

#define ISSUE_S(stg_, idx2) do { \
        const int ntp_ = (idx2) / NKC, kc_ = (idx2) % NKC; \
        uint32_t db = BST + (stg_) * 8192 + tid * 16; \
        const unsigned char* s0 = g_Bpl + ((size_t)((ntp_ * 2 + 0) * NKC + kc_) << 12) + tid * 16; \
        const unsigned char* s1 = g_Bpl + ((size_t)((ntp_ * 2 + 1) * NKC + kc_) << 12) + tid * 16; \
        CP16(db,        s0); \
        CP16(db + 4096, s1); \
        CP_COMMIT(); \
    } while (0)

    ISSUE_S(0, 0);
    ISSUE_S(1, 1);

    // ---- Phase 1: convert A once (2x-scaled HI fp16 plane) ----
    {
        const int p = tid & 63;
        const int q = tid >> 6;            // (kc-half, oct)
        const int m = mblk * 64 + p;
        const float* xs = x + (m >> 12) * (CC * HWS) + (m & 4095);
#pragma unroll
        for (int base = 0; base < NKC; base += 2) {
            const int kc = base + (q >> 1);
            const int oct = q & 1;
            uint32_t hu[4];
#pragma unroll
            for (int kk = 0; kk < 8; kk += 2) {
                const int ka = kc * 16 + oct * 8 + kk;
                __half h0 = __float2half_rn(2.f * xs[(size_t)ka * HWS]);
                __half h1 = __float2half_rn(2.f * xs[(size_t)(ka + 1) * HWS]);
                hu[kk >> 1] = (uint32_t)__half_as_ushort(h0) | ((uint32_t)__half_as_ushort(h1) << 16);
            }
            *(uint4*)(smdyn + APL_OFF + kc * 2048 + oct * 1024 + p * 16) = *(uint4*)hu;
        }
    }

    float c[2][8][4];
#pragma unroll
    for (int a = 0; a < 2; a++)
#pragma unroll
        for (int b = 0; b < 8; b++)
#pragma unroll
            for (int r = 0; r < 4; r++) c[a][b][r] = 0.f;
    float bS1[4], bS2[4];
    int   bI1[4];
#pragma unroll
    for (int r = 0; r < 4; r++) { bS1[r] = -3.4e38f; bS2[r] = -3.4e38f; bI1[r] = 0; }

    const int g = lane >> 3;
    const int kk2 = ((g & 1) << 3) | (lane & 7);
    const int nbg = g >> 1;
    const int h = wn0 >> 7;          // which 4KB chunk within the stage
    const int ln0 = wn0 & 127;

    int stg = 0;
    for (int ii = 0; ii < NIT; ii++) {
        const int ntp = ii / NKC, kc = ii % NKC;
        if (ii + 1 < NIT) CP_WAIT1(); else CP_WAIT0();
        __syncthreads();
        if (ii + 2 < NIT) ISSUE_S((stg + 2) % NSTG, ii + 2);

        const uint32_t sB = BST + stg * 8192 + h * 4096;

        // B fragments (hi plane): [unit-pair 4][4 regs]
        uint32_t bf[4][4];
#pragma unroll
        for (int np = 0; np < 4; np++) {
            const int nblk = ((ln0 + np * 16) >> 3) + nbg;
            const uint32_t addr = sB + kk2 * 256 +
                (((nblk & 8) | ((nblk ^ (kk2 & 7)) & 7)) << 4);
            LDSM_X4_T(bf[np][0], bf[np][1], bf[np][2], bf[np][3], addr);
        }
#pragma unroll
        for (int mt = 0; mt < 2; mt++) {
            const int mrow = wm0 + mt * 16 + (g & 1) * 8 + (lane & 7);
            uint32_t aH[4];
            const uint32_t aaddr = APL + kc * 2048 + (g >> 1) * 1024 + mrow * 16;
            LDSM_X4(aH[0], aH[1], aH[2], aH[3], aaddr);
#pragma unroll
            for (int np = 0; np < 4; np++) {
                MMA16816(c[mt][2*np],   aH[0],aH[1],aH[2],aH[3], bf[np][0], bf[np][1]);
                MMA16816(c[mt][2*np+1], aH[0],aH[1],aH[2],aH[3], bf[np][2], bf[np][3]);
            }
        }

        if (kc == NKC - 1) {
            // scores = c - |e|^2; track best1/best2 (ascending n, strict >), reset
            const int nb0 = ntp * 256 + wn0 + (lane & 3) * 2;
#pragma unroll
            for (int tn = 0; tn < 8; tn++) {
                const int n = nb0 + tn * 8;
                const float nr0 = __ldg(&g_embed_norm[n]);
                const float nr1 = __ldg(&g_embed_norm[n + 1]);
#pragma unroll
                for (int mt = 0; mt < 2; mt++) {
                    const int b0 = mt * 2, b1 = mt * 2 + 1;
                    const float s0 = c[mt][tn][0] - nr0;
                    const float s1 = c[mt][tn][1] - nr1;
                    const float s2 = c[mt][tn][2] - nr0;
                    const float s3 = c[mt][tn][3] - nr1;
                    if (s0 > bS1[b0]) { bS2[b0] = bS1[b0]; bS1[b0] = s0; bI1[b0] = n; }
                    else if (s0 > bS2[b0]) bS2[b0] = s0;
                    if (s1 > bS1[b0]) { bS2[b0] = bS1[b0]; bS1[b0] = s1; bI1[b0] = n + 1; }
                    else if (s1 > bS2[b0]) bS2[b0] = s1;
                    if (s2 > bS1[b1]) { bS2[b1] = bS1[b1]; bS1[b1] = s2; bI1[b1] = n; }
                    else if (s2 > bS2[b1]) bS2[b1] = s2;
                    if (s3 > bS1[b1]) { bS2[b1] = bS1[b1]; bS1[b1] = s3; bI1[b1] = n + 1; }
                    else if (s3 > bS2[b1]) bS2[b1] = s3;
                    c[mt][tn][0] = 0.f; c[mt][tn][1] = 0.f;
                    c[mt][tn][2] = 0.f; c[mt][tn][3] = 0.f;
                }
            }
        }
        stg = (stg + 1) % NSTG;
    }

    __syncthreads();  // drained; reuse A-plane smem for reduction scratch
    float* redS1 = (float*)smdyn;            // [4][64]
    int*   redI1 = (int*)(smdyn + 1024);
    float* redS2 = (float*)(smdyn + 2048);

    // merge (s1,i1,s2) across lane quads
    float rs1[4], rs2[4]; int ri1[4];
#pragma unroll
    for (int r = 0; r < 4; r++) {
        float s1 = bS1[r], s2 = bS2[r]; int i1 = bI1[r];
#pragma unroll
        for (int off = 1; off <= 2; off <<= 1) {
            float os1 = __shfl_xor_sync(0xffffffffu, s1, off);
            int   oi1 = __shfl_xor_sync(0xffffffffu, i1, off);
            float os2 = __shfl_xor_sync(0xffffffffu, s2, off);
            if (os1 > s1 || (os1 == s1 && oi1 < i1)) {
                s2 = fmaxf(s1, os2); s1 = os1; i1 = oi1;
            } else {
                s2 = fmaxf(s2, os1);
            }
        }
        rs1[r] = s1; rs2[r] = s2; ri1[r] = i1;
    }
    if ((lane & 3) == 0) {
#pragma unroll
        for (int r = 0; r < 4; r++) {
            const int rl = wm0 + (r >> 1) * 16 + (r & 1) * 8 + (lane >> 2);
            redS1[ncol * 64 + rl] = rs1[r];
            redI1[ncol * 64 + rl] = ri1[r];
            redS2[ncol * 64 + rl] = rs2[r];
        }
    }
    __syncthreads();
    if (ncol == 0 && (lane & 3) == 0) {
#pragma unroll
        for (int r = 0; r < 4; r++) {
            const int rl = wm0 + (r >> 1) * 16 + (r & 1) * 8 + (lane >> 2);
            float s1 = redS1[rl], s2 = redS2[rl]; int i1 = redI1[rl];
#pragma unroll
            for (int cix = 1; cix < 4; cix++) {
                const float os1 = redS1[cix * 64 + rl];
                const int   oi1 = redI1[cix * 64 + rl];
                const float os2 = redS2[cix * 64 + rl];
                if (os1 > s1 || (os1 == s1 && oi1 < i1)) {
                    s2 = fmaxf(s1, os2); s1 = os1; i1 = oi1;
                } else {
                    s2 = fmaxf(s2, os1);
                }
            }
            const int mm = mblk * 64 + rl;
            g_ids[mm] = i1;
            const int sp = mm & 4095;
            out_ids[(mm & ~4095) | ((sp & 63) << 6) | (sp >> 6)] = (float)i1;
            if (s1 - s2 < TAU) {
                const int pos = atomicAdd(&g_nfix, 1);
                g_fix[pos] = mm;
            }
        }
    }
}

// ---------------------------------------------------------------------------
// k_fix: exact fp32 rescore of flagged pixels against ALL 2048 codes.
// Block handles 32 pixels; embed tiled 8 rows at a time through smem.
// Thread (px=tid>>3, cl=tid&7) owns pixel px, codes = cl (mod 8).
// ---------------------------------------------------------------------------
__global__ __launch_bounds__(256) void k_fix(const float* __restrict__ x,
                                             const float* __restrict__ embed,
                                             float* __restrict__ out_ids) {
    __shared__ float xs[32][272];   // padded: conflict-free float4
    __shared__ float es[8 * 272];
    __shared__ int   pl[32];
    __shared__ float rS[32][8];
    __shared__ int   rI[32][8];
    const int tid = threadIdx.x;
    const int nfix = g_nfix;

    for (int base = blockIdx.x * 32; base < nfix; base += gridDim.x * 32) {
        const int cnt = min(32, nfix - base);
        if (tid < 32) pl[tid] = (tid < cnt) ? g_fix[base + tid] : 0;
        __syncthreads();
        for (int idx = tid; idx < 32 * 256; idx += 256) {
            const int px = idx >> 8, ch = idx & 255;
            float v = 0.f;
            if (px < cnt) {
                const int m = pl[px];
                v = x[(size_t)(m >> 12) * (CC * HWS) + (size_t)ch * HWS + (m & 4095)];
            }
            xs[px][ch] = v;
        }
        __syncthreads();

        const int px = tid >> 3, cl = tid & 7;
        float bs = -3.4e38f; int bi = 0;
        for (int c0 = 0; c0 < DD; c0 += 8) {
            // stage 8 embed rows (2048 contiguous floats), padded layout
            {
                const float* src = embed + (size_t)c0 * CC + tid * 8;
                float4 v0 = *(const float4*)src;
                float4 v1 = *(const float4*)(src + 4);
                const int r = (tid * 8) >> 8;
                const int ch = (tid * 8) & 255;
                float* dst = es + r * 272 + ch;
                dst[0] = v0.x; dst[1] = v0.y; dst[2] = v0.z; dst[3] = v0.w;
                dst[4] = v1.x; dst[5] = v1.y; dst[6] = v1.z; dst[7] = v1.w;
            }
            __syncthreads();
            if (px < cnt) {
                const float* er = es + cl * 272;
                const float* xr = xs[px];
                float d0 = 0.f, d1 = 0.f, d2 = 0.f, d3 = 0.f;
#pragma unroll 16
                for (int ch = 0; ch < 256; ch += 4) {
                    float4 xv = *(const float4*)(xr + ch);
                    float4 ev = *(const float4*)(er + ch);
                    d0 = fmaf(xv.x, ev.x, d0);
                    d1 = fmaf(xv.y, ev.y, d1);
                    d2 = fmaf(xv.z, ev.z, d2);
                    d3 = fmaf(xv.w, ev.w, d3);
                }
                const int d = c0 + cl;
                const float sc = fmaf(2.f, (d0 + d1) + (d2 + d3), -__ldg(&g_embed_norm[d]));
                if (sc > bs) { bs = sc; bi = d; }
            }
            __syncthreads();
        }
        rS[px][cl] = bs; rI[px][cl] = bi;
        __syncthreads();
        if (cl == 0 && px < cnt) {
            float s = rS[px][0]; int i = rI[px][0];
#pragma unroll
            for (int j = 1; j < 8; j++) {
                const float so = rS[px][j]; const int io = rI[px][j];
                if (so > s || (so == s && io < i)) { s = so; i = io; }
            }
            const int m = pl[px];
            g_ids[m] = i;
            const int sp = m & 4095;
            out_ids[(m & ~4095) | ((sp & 63) << 6) | (sp >> 6)] = (float)i;
        }
        __syncthreads();
    }
}

// ---------------------------------------------------------------------------
// K2: quantized write + commit-loss SSE + segment sums (proven R1 code)
// ---------------------------------------------------------------------------
__global__ __launch_bounds__(256)
void k_quant(const float* __restrict__ x, const float* __restrict__ embed,
             float* __restrict__ out_q) {
    __shared__ float qs[32][257];
    __shared__ int   sid[32];
    __shared__ float red[8];

    const int t = threadIdx.x;
    const int lane = t & 31, warp = t >> 5;
    const int m0 = blockIdx.x * 32;
    const int b = m0 >> 12;
    const int s0 = m0 & 4095;

    if (t < 32) sid[t] = g_ids[m0 + t];
    __syncthreads();
#pragma unroll
    for (int r = 0; r < 4; r++) {
        const int pp = warp + r * 8;
        const float* row = embed + sid[pp] * CC;
#pragma unroll
        for (int jj = 0; jj < 8; jj++) qs[pp][lane + 32 * jj] = row[lane + 32 * jj];
    }
    __syncthreads();

    const float* xb = x + b * (CC * HWS) + s0;
    float* qb = out_q + b * (CC * HWS) + s0;
    const int myid = sid[lane];
    float lsum = 0.f;
#pragma unroll
    for (int ci = 0; ci < 32; ci++) {
        const int cc = warp + ci * 8;
        float xv = xb[cc * HWS + lane];
        float qv = qs[lane][cc];
        qb[cc * HWS + lane] = qv;
        float dd = xv - qv;
        lsum = fmaf(dd, dd, lsum);
        atomicAdd(&g_embed_sum[cc * DD + myid], xv);
    }
    if (warp == 0) atomicAdd(&g_counts[myid], 1.0f);

#pragma unroll
    for (int o = 16; o; o >>= 1) lsum += __shfl_xor_sync(0xffffffffu, lsum, o);
    if (lane == 0) red[warp] = lsum;
    __syncthreads();
    if (t == 0) {
        float s = 0.f;
#pragma unroll
        for (int i = 0; i < 8; i++) s += red[i];
        atomicAdd(&g_sse, s);
    }
}

__global__ void k_stats(const float* __restrict__ cs, float* __restrict__ out_ncs,
                        float* __restrict__ out_loss) {
    __shared__ float red[32];
    const int t = threadIdx.x;
    const int d0 = t, d1 = t + 1024;
    float n0 = MOM * cs[d0] + OMM * g_counts[d0];
    float n1 = MOM * cs[d1] + OMM * g_counts[d1];
    out_ncs[d0] = n0;
    out_ncs[d1] = n1;
    float s = n0 + n1;
#pragma unroll
    for (int o = 16; o; o >>= 1) s += __shfl_xor_sync(0xffffffffu, s, o);
    if ((t & 31) == 0) red[t >> 5] = s;
    __syncthreads();
    if (t < 32) {
        float v = red[t];
#pragma unroll
        for (int o = 16; o; o >>= 1) v += __shfl_xor_sync(0xffffffffu, v, o);
        if (t == 0) red[0] = v;
    }
    __syncthreads();
    const float n = red[0];
    const float scale = (n + (float)DD * EPSV) / n;
    g_inv_cs[d0] = scale / (n0 + EPSV);
    g_inv_cs[d1] = scale / (n1 + EPSV);
    if (t == 0) out_loss[0] = g_sse * (1.f / 16777216.f);
}

__global__ void k_embed_out(const float* __restrict__ embed_avg,
                            float* __restrict__ out_nea, float* __restrict__ out_ne) {
    const int idx = blockIdx.x * 256 + threadIdx.x;
    const int cc = idx >> 11, d = idx & 2047;
    float nea = MOM * embed_avg[idx] + OMM * g_embed_sum[idx];
    out_nea[idx] = nea;
    out_ne[d * CC + cc] = nea * g_inv_cs[d];
}

// ---------------------------------------------------------------------------
extern "C" void kernel_launch(void* const* d_in, const int* in_sizes, int n_in,
                              void* d_out, int out_size) {
    const float* x     = (const float*)d_in[0];
    const float* embed = (const float*)d_in[1];
    const float* cs    = (const float*)d_in[2];
    const float* ea    = (const float*)d_in[3];
    float* out = (float*)d_out;

    cudaFuncSetAttribute(k_screen, cudaFuncAttributeMaxDynamicSharedMemorySize, SMEM_DYN);

    k_zero<<<(CC * DD + DD + 2 + 255) / 256, 256>>>();
    k_norm<<<DD / 8, 256>>>(embed);
    prep_B<<<16 * NKC, 256>>>(embed);
    k_screen<<<NPIX / 64, 256, SMEM_DYN>>>(x, out + OFF_IDS);
    k_fix<<<256, 256>>>(x, embed, out + OFF_IDS);
    k_quant<<<NPIX / 32, 256>>>(x, embed, out + OFF_Q);
    k_stats<<<1, 1024>>>(cs, out + OFF_NCS, out + OFF_LOSS);
    k_embed_out<<<(CC * DD) / 256, 256>>>(ea, out + OFF_NEA, out + OFF_NE);
}

// round 15
// speedup vs baseline: 3.2850x; 3.2850x over previous
#include <cuda_runtime.h>
#include <cuda_fp16.h>
#include <cstdint>

// Problem constants
#define BB 16
#define CC 256
#define HWS 4096
#define NPIX 65536
#define DD 2048
#define MOM 0.99f
#define OMM 0.01f
#define EPSV 1e-5f

// Output layout (float32, reference return order)
#define OFF_Q    0
#define OFF_LOSS 16777216
#define OFF_IDS  16777217
#define OFF_NE   16842753
#define OFF_NCS  17367041
#define OFF_NEA  17369089

#define NKC 16            // K chunks of 16 (K=256)
#define NTP 8             // N-tile pairs (2048 codes / 256)
#define NIT (NTP * NKC)   // 128 mainloop iterations
#define NSTG 3            // cp.async pipeline stages
#define TAU 0.15f         // screen ambiguity threshold

// Screen smem (per CTA = 57344 B -> 2 CTAs/SM)
#define SAPL_OFF 0        // A hi plane: [kc 16][oct 2][px 64] x 16B = 32768
#define SBST_OFF 32768    // B stages: 3 x 8192 = 24576
#define SMEM_SCREEN 57344

// Fix smem (per CTA = 114688 B -> 2 CTAs/SM), R10 layout
#define FAPL_OFF 0        // A planes: [kc 16][plane 2][oct 2][px 64] x 16B = 65536
#define FBST_OFF 65536    // B stages: 3 x 16384
#define SMEM_FIX 114688

// Scratch (small device globals only)
__device__ __align__(16) unsigned char g_Bpl[16u*NKC*8192u]; // [ntile][kchunk] 8KB: hi(4KB)+lo(4KB) fp16 embed planes
__device__ float g_embed_norm[DD];
__device__ int   g_ids[NPIX];
__device__ float g_counts[DD];
__device__ float g_embed_sum[CC * DD];
__device__ float g_inv_cs[DD];
__device__ float g_sse;
__device__ int   g_nfix;
__device__ int   g_fix[NPIX];

// ---------------- PTX helpers (sm_80-baseline features only) ----------------
__device__ __forceinline__ uint32_t smem_u32(const void* p) {
    uint32_t a;
    asm("{ .reg .u64 t; cvta.to.shared.u64 t, %1; cvt.u32.u64 %0, t; }" : "=r"(a) : "l"(p));
    return a;
}
#define CP16(dst, src) asm volatile("cp.async.cg.shared.global [%0], [%1], 16;" :: "r"(dst), "l"(src))
#define CP_COMMIT() asm volatile("cp.async.commit_group;" ::: "memory")
#define CP_WAIT1()  asm volatile("cp.async.wait_group 1;" ::: "memory")
#define CP_WAIT0()  asm volatile("cp.async.wait_group 0;" ::: "memory")

#define LDSM_X4(r0,r1,r2,r3,addr) \
    asm volatile("ldmatrix.sync.aligned.m8n8.x4.shared.b16 {%0,%1,%2,%3}, [%4];" \
        : "=r"(r0),"=r"(r1),"=r"(r2),"=r"(r3) : "r"(addr))
#define LDSM_X4_T(r0,r1,r2,r3,addr) \
    asm volatile("ldmatrix.sync.aligned.m8n8.x4.trans.shared.b16 {%0,%1,%2,%3}, [%4];" \
        : "=r"(r0),"=r"(r1),"=r"(r2),"=r"(r3) : "r"(addr))

#define MMA16816(c, a0,a1,a2,a3, b0,b1) \
    asm volatile("mma.sync.aligned.m16n8k16.row.col.f32.f16.f16.f32 " \
        "{%0,%1,%2,%3}, {%4,%5,%6,%7}, {%8,%9}, {%0,%1,%2,%3};" \
        : "+f"((c)[0]),"+f"((c)[1]),"+f"((c)[2]),"+f"((c)[3]) \
        : "r"(a0),"r"(a1),"r"(a2),"r"(a3),"r"(b0),"r"(b1))

// ---------------------------------------------------------------------------
__global__ void k_zero() {
    int idx = blockIdx.x * 256 + threadIdx.x;
    if (idx < CC * DD)                 g_embed_sum[idx] = 0.f;
    else if (idx < CC * DD + DD)       g_counts[idx - CC * DD] = 0.f;
    else if (idx == CC * DD + DD)      g_sse = 0.f;
    else if (idx == CC * DD + DD + 1)  g_nfix = 0;
}

__global__ void k_norm(const float* __restrict__ embed) {
    int warp = threadIdx.x >> 5, lane = threadIdx.x & 31;
    int d = blockIdx.x * 8 + warp;
    const float* row = embed + d * CC;
    float s = 0.f;
#pragma unroll
    for (int j = 0; j < 8; j++) { float v = row[lane + 32 * j]; s = fmaf(v, v, s); }
#pragma unroll
    for (int o = 16; o; o >>= 1) s += __shfl_xor_sync(0xffffffffu, s, o);
    if (lane == 0) g_embed_norm[d] = s;
}

// ---------------------------------------------------------------------------
// prep_B: embed -> fp16 hi/lo planes. Chunk (nt,kc) = 8KB: hi@0, lo@4096.
// Each plane: [k 16][swizzled 16B unit = 8 consecutive n], conflict-free ldsm.trans
// ---------------------------------------------------------------------------
__global__ __launch_bounds__(256) void prep_B(const float* __restrict__ embed) {
    const int nt = blockIdx.x / NKC, kc = blockIdx.x % NKC;
    const int t = threadIdx.x;
    const int k = t >> 4, nblk = t & 15;
    const int kglob = kc * 16 + k;
    const int n0 = nt * 128 + nblk * 8;
    uint32_t hu[4], lu[4];
#pragma unroll
    for (int nn = 0; nn < 8; nn += 2) {
        float v0 = embed[(n0 + nn) * CC + kglob];
        float v1 = embed[(n0 + nn + 1) * CC + kglob];
        __half h0 = __float2half_rn(v0), h1 = __float2half_rn(v1);
        __half l0 = __float2half_rn(v0 - __half2float(h0));
        __half l1 = __float2half_rn(v1 - __half2float(h1));
        hu[nn >> 1] = (uint32_t)__half_as_ushort(h0) | ((uint32_t)__half_as_ushort(h1) << 16);
        lu[nn >> 1] = (uint32_t)__half_as_ushort(l0) | ((uint32_t)__half_as_ushort(l1) << 16);
    }
    const int swz = (nblk & 8) | ((nblk ^ (k & 7)) & 7);
    unsigned char* ob = g_Bpl + ((size_t)(nt * NKC + kc) << 13);
    *(uint4*)(ob + k * 256 + swz * 16) = *(uint4*)hu;
    *(uint4*)(ob + 4096 + k * 256 + swz * 16) = *(uint4*)lu;
}

// ---------------------------------------------------------------------------
// k_screen: fp16-hi 1-MMA screening GEMM + top-2 argmax; flags gap < TAU.
// ---------------------------------------------------------------------------
__global__ __launch_bounds__(256, 2) void k_screen(const float* __restrict__ x,
                                                   float* __restrict__ out_ids) {
    extern __shared__ __align__(16) unsigned char smdyn[];
    const uint32_t sbase = smem_u32(smdyn);
    const uint32_t APL = sbase + SAPL_OFF;
    const uint32_t BST = sbase + SBST_OFF;
    const int tid = threadIdx.x;
    const int lane = tid & 31, wid = tid >> 5;
    const int wm0 = (wid >> 2) * 32;
    const int ncol = wid & 3;
    const int wn0 = ncol * 64;
    const int mblk = blockIdx.x;

#define ISSUE_S(stg_, idx2) do { \
        const int ntp_ = (idx2) / NKC, kc_ = (idx2) % NKC; \
        uint32_t db = BST + (stg_) * 8192 + tid * 16; \
        const unsigned char* s0 = g_Bpl + ((size_t)((ntp_ * 2 + 0) * NKC + kc_) << 13) + tid * 16; \
        const unsigned char* s1 = g_Bpl + ((size_t)((ntp_ * 2 + 1) * NKC + kc_) << 13) + tid * 16; \
        CP16(db,        s0); \
        CP16(db + 4096, s1); \
        CP_COMMIT(); \
    } while (0)

    ISSUE_S(0, 0);
    ISSUE_S(1, 1);

    // ---- Phase 1: convert A once (2x-scaled HI fp16 plane) ----
    {
        const int p = tid & 63;
        const int q = tid >> 6;
        const int m = mblk * 64 + p;
        const float* xs = x + (m >> 12) * (CC * HWS) + (m & 4095);
#pragma unroll
        for (int base = 0; base < NKC; base += 2) {
            const int kc = base + (q >> 1);
            const int oct = q & 1;
            uint32_t hu[4];
#pragma unroll
            for (int kk = 0; kk < 8; kk += 2) {
                const int ka = kc * 16 + oct * 8 + kk;
                __half h0 = __float2half_rn(2.f * xs[(size_t)ka * HWS]);
                __half h1 = __float2half_rn(2.f * xs[(size_t)(ka + 1) * HWS]);
                hu[kk >> 1] = (uint32_t)__half_as_ushort(h0) | ((uint32_t)__half_as_ushort(h1) << 16);
            }
            *(uint4*)(smdyn + SAPL_OFF + kc * 2048 + oct * 1024 + p * 16) = *(uint4*)hu;
        }
    }

    float c[2][8][4];
#pragma unroll
    for (int a = 0; a < 2; a++)
#pragma unroll
        for (int b = 0; b < 8; b++)
#pragma unroll
            for (int r = 0; r < 4; r++) c[a][b][r] = 0.f;
    float bS1[4], bS2[4];
    int   bI1[4];
#pragma unroll
    for (int r = 0; r < 4; r++) { bS1[r] = -3.4e38f; bS2[r] = -3.4e38f; bI1[r] = 0; }

    const int g = lane >> 3;
    const int kk2 = ((g & 1) << 3) | (lane & 7);
    const int nbg = g >> 1;
    const int h = wn0 >> 7;
    const int ln0 = wn0 & 127;

    int stg = 0;
    for (int ii = 0; ii < NIT; ii++) {
        const int ntp = ii / NKC, kc = ii % NKC;
        if (ii + 1 < NIT) CP_WAIT1(); else CP_WAIT0();
        __syncthreads();
        if (ii + 2 < NIT) ISSUE_S((stg + 2) % NSTG, ii + 2);

        const uint32_t sB = BST + stg * 8192 + h * 4096;

        uint32_t bf[4][4];
#pragma unroll
        for (int np = 0; np < 4; np++) {
            const int nblk = ((ln0 + np * 16) >> 3) + nbg;
            const uint32_t addr = sB + kk2 * 256 +
                (((nblk & 8) | ((nblk ^ (kk2 & 7)) & 7)) << 4);
            LDSM_X4_T(bf[np][0], bf[np][1], bf[np][2], bf[np][3], addr);
        }
#pragma unroll
        for (int mt = 0; mt < 2; mt++) {
            const int mrow = wm0 + mt * 16 + (g & 1) * 8 + (lane & 7);
            uint32_t aH[4];
            const uint32_t aaddr = APL + kc * 2048 + (g >> 1) * 1024 + mrow * 16;
            LDSM_X4(aH[0], aH[1], aH[2], aH[3], aaddr);
#pragma unroll
            for (int np = 0; np < 4; np++) {
                MMA16816(c[mt][2*np],   aH[0],aH[1],aH[2],aH[3], bf[np][0], bf[np][1]);
                MMA16816(c[mt][2*np+1], aH[0],aH[1],aH[2],aH[3], bf[np][2], bf[np][3]);
            }
        }

        if (kc == NKC - 1) {
            const int nb0 = ntp * 256 + wn0 + (lane & 3) * 2;
#pragma unroll
            for (int tn = 0; tn < 8; tn++) {
                const int n = nb0 + tn * 8;
                const float nr0 = __ldg(&g_embed_norm[n]);
                const float nr1 = __ldg(&g_embed_norm[n + 1]);
#pragma unroll
                for (int mt = 0; mt < 2; mt++) {
                    const int b0 = mt * 2, b1 = mt * 2 + 1;
                    const float s0 = c[mt][tn][0] - nr0;
                    const float s1 = c[mt][tn][1] - nr1;
                    const float s2 = c[mt][tn][2] - nr0;
                    const float s3 = c[mt][tn][3] - nr1;
                    if (s0 > bS1[b0]) { bS2[b0] = bS1[b0]; bS1[b0] = s0; bI1[b0] = n; }
                    else if (s0 > bS2[b0]) bS2[b0] = s0;
                    if (s1 > bS1[b0]) { bS2[b0] = bS1[b0]; bS1[b0] = s1; bI1[b0] = n + 1; }
                    else if (s1 > bS2[b0]) bS2[b0] = s1;
                    if (s2 > bS1[b1]) { bS2[b1] = bS1[b1]; bS1[b1] = s2; bI1[b1] = n; }
                    else if (s2 > bS2[b1]) bS2[b1] = s2;
                    if (s3 > bS1[b1]) { bS2[b1] = bS1[b1]; bS1[b1] = s3; bI1[b1] = n + 1; }
                    else if (s3 > bS2[b1]) bS2[b1] = s3;
                    c[mt][tn][0] = 0.f; c[mt][tn][1] = 0.f;
                    c[mt][tn][2] = 0.f; c[mt][tn][3] = 0.f;
                }
            }
        }
        stg = (stg + 1) % NSTG;
    }

    __syncthreads();
    float* redS1 = (float*)smdyn;
    int*   redI1 = (int*)(smdyn + 1024);
    float* redS2 = (float*)(smdyn + 2048);

    float rs1[4], rs2[4]; int ri1[4];
#pragma unroll
    for (int r = 0; r < 4; r++) {
        float s1 = bS1[r], s2 = bS2[r]; int i1 = bI1[r];
#pragma unroll
        for (int off = 1; off <= 2; off <<= 1) {
            float os1 = __shfl_xor_sync(0xffffffffu, s1, off);
            int   oi1 = __shfl_xor_sync(0xffffffffu, i1, off);
            float os2 = __shfl_xor_sync(0xffffffffu, s2, off);
            if (os1 > s1 || (os1 == s1 && oi1 < i1)) {
                s2 = fmaxf(s1, os2); s1 = os1; i1 = oi1;
            } else {
                s2 = fmaxf(s2, os1);
            }
        }
        rs1[r] = s1; rs2[r] = s2; ri1[r] = i1;
    }
    if ((lane & 3) == 0) {
#pragma unroll
        for (int r = 0; r < 4; r++) {
            const int rl = wm0 + (r >> 1) * 16 + (r & 1) * 8 + (lane >> 2);
            redS1[ncol * 64 + rl] = rs1[r];
            redI1[ncol * 64 + rl] = ri1[r];
            redS2[ncol * 64 + rl] = rs2[r];
        }
    }
    __syncthreads();
    if (ncol == 0 && (lane & 3) == 0) {
#pragma unroll
        for (int r = 0; r < 4; r++) {
            const int rl = wm0 + (r >> 1) * 16 + (r & 1) * 8 + (lane >> 2);
            float s1 = redS1[rl], s2 = redS2[rl]; int i1 = redI1[rl];
#pragma unroll
            for (int cix = 1; cix < 4; cix++) {
                const float os1 = redS1[cix * 64 + rl];
                const int   oi1 = redI1[cix * 64 + rl];
                const float os2 = redS2[cix * 64 + rl];
                if (os1 > s1 || (os1 == s1 && oi1 < i1)) {
                    s2 = fmaxf(s1, os2); s1 = os1; i1 = oi1;
                } else {
                    s2 = fmaxf(s2, os1);
                }
            }
            const int mm = mblk * 64 + rl;
            g_ids[mm] = i1;
            const int sp = mm & 4095;
            out_ids[(mm & ~4095) | ((sp & 63) << 6) | (sp >> 6)] = (float)i1;
            if (s1 - s2 < TAU) {
                const int pos = atomicAdd(&g_nfix, 1);
                g_fix[pos] = mm;
            }
        }
    }
}

// ---------------------------------------------------------------------------
// k_fix_mma: exact 3xFP16 rescore of flagged pixels (R10 mainloop, gathered A).
// Tile t = 64 pixels from g_fix[t*64 ..]. Blocks with no work exit immediately.
// ---------------------------------------------------------------------------
__global__ __launch_bounds__(256, 2) void k_fix_mma(const float* __restrict__ x,
                                                    float* __restrict__ out_ids) {
    const int nfix = g_nfix;
    const int t0 = blockIdx.x;
    if (t0 * 64 >= nfix) return;

    extern __shared__ __align__(16) unsigned char smdyn[];
    const uint32_t sbase = smem_u32(smdyn);
    const uint32_t APL = sbase + FAPL_OFF;
    const uint32_t BST = sbase + FBST_OFF;
    const int tid = threadIdx.x;
    const int lane = tid & 31, wid = tid >> 5;
    const int wm0 = (wid >> 2) * 32;
    const int ncol = wid & 3;
    const int wn0 = ncol * 64;

#define ISSUE_F(stg_, idx2) do { \
        const int ntp_ = (idx2) / NKC, kc_ = (idx2) % NKC; \
        uint32_t db = BST + (stg_) * 16384 + tid * 16; \
        const unsigned char* s0 = g_Bpl + ((size_t)((ntp_ * 2 + 0) * NKC + kc_) << 13) + tid * 16; \
        const unsigned char* s1 = g_Bpl + ((size_t)((ntp_ * 2 + 1) * NKC + kc_) << 13) + tid * 16; \
        CP16(db,          s0); \
        CP16(db + 4096,   s0 + 4096); \
        CP16(db + 8192,   s1); \
        CP16(db + 12288,  s1 + 4096); \
        CP_COMMIT(); \
    } while (0)

    ISSUE_F(0, 0);
    ISSUE_F(1, 1);

    // ---- Phase 1: convert gathered A (2x-scaled hi/lo fp16 planes) ----
    {
        const int p = tid & 63;
        const int q = tid >> 6;
        const int slot = t0 * 64 + p;
        const int m = g_fix[slot < nfix ? slot : nfix - 1];
        const float* xs = x + (m >> 12) * (CC * HWS) + (m & 4095);
#pragma unroll
        for (int base = 0; base < NKC; base += 2) {
            const int kc = base + (q >> 1);
            const int oct = q & 1;
            uint32_t hu[4], lu[4];
#pragma unroll
            for (int kk = 0; kk < 8; kk += 2) {
                const int ka = kc * 16 + oct * 8 + kk;
                float v0 = 2.f * xs[(size_t)ka * HWS];
                float v1 = 2.f * xs[(size_t)(ka + 1) * HWS];
                __half h0 = __float2half_rn(v0), h1 = __float2half_rn(v1);
                __half l0 = __float2half_rn(v0 - __half2float(h0));
                __half l1 = __float2half_rn(v1 - __half2float(h1));
                hu[kk >> 1] = (uint32_t)__half_as_ushort(h0) | ((uint32_t)__half_as_ushort(h1) << 16);
                lu[kk >> 1] = (uint32_t)__half_as_ushort(l0) | ((uint32_t)__half_as_ushort(l1) << 16);
            }
            *(uint4*)(smdyn + FAPL_OFF + kc * 4096 + oct * 1024 + p * 16)        = *(uint4*)hu;
            *(uint4*)(smdyn + FAPL_OFF + kc * 4096 + 2048 + oct * 1024 + p * 16) = *(uint4*)lu;
        }
    }

    float c[2][8][4];
#pragma unroll
    for (int a = 0; a < 2; a++)
#pragma unroll
        for (int b = 0; b < 8; b++)
#pragma unroll
            for (int r = 0; r < 4; r++) c[a][b][r] = 0.f;
    float bestS[4];
    int   bestI[4];
#pragma unroll
    for (int r = 0; r < 4; r++) { bestS[r] = -3.4e38f; bestI[r] = 0; }

    const int g = lane >> 3;
    const int kk2 = ((g & 1) << 3) | (lane & 7);
    const int nbg = g >> 1;
    const int h = wn0 >> 7;
    const int ln0 = wn0 & 127;

    int stg = 0;
    for (int ii = 0; ii < NIT; ii++) {
        const int ntp = ii / NKC, kc = ii % NKC;
        if (ii + 1 < NIT) CP_WAIT1(); else CP_WAIT0();
        __syncthreads();
        if (ii + 2 < NIT) ISSUE_F((stg + 2) % NSTG, ii + 2);

        const uint32_t sB = BST + stg * 16384 + h * 8192;

        uint32_t bf[2][4][4];
#pragma unroll
        for (int pp = 0; pp < 2; pp++)
#pragma unroll
            for (int np = 0; np < 4; np++) {
                const int nblk = ((ln0 + np * 16) >> 3) + nbg;
                const uint32_t addr = sB + pp * 4096 + kk2 * 256 +
                    (((nblk & 8) | ((nblk ^ (kk2 & 7)) & 7)) << 4);
                LDSM_X4_T(bf[pp][np][0], bf[pp][np][1], bf[pp][np][2], bf[pp][np][3], addr);
            }
#pragma unroll
        for (int mt = 0; mt < 2; mt++) {
            const int mrow = wm0 + mt * 16 + (g & 1) * 8 + (lane & 7);
            uint32_t aH[4], aL[4];
            const uint32_t aaddr = APL + kc * 4096 + (g >> 1) * 1024 + mrow * 16;
            LDSM_X4(aH[0], aH[1], aH[2], aH[3], aaddr);
            LDSM_X4(aL[0], aL[1], aL[2], aL[3], aaddr + 2048);
#pragma unroll
            for (int np = 0; np < 4; np++) {
                MMA16816(c[mt][2*np],   aH[0],aH[1],aH[2],aH[3], bf[0][np][0], bf[0][np][1]);
                MMA16816(c[mt][2*np],   aH[0],aH[1],aH[2],aH[3], bf[1][np][0], bf[1][np][1]);
                MMA16816(c[mt][2*np],   aL[0],aL[1],aL[2],aL[3], bf[0][np][0], bf[0][np][1]);
                MMA16816(c[mt][2*np+1], aH[0],aH[1],aH[2],aH[3], bf[0][np][2], bf[0][np][3]);
                MMA16816(c[mt][2*np+1], aH[0],aH[1],aH[2],aH[3], bf[1][np][2], bf[1][np][3]);
                MMA16816(c[mt][2*np+1], aL[0],aL[1],aL[2],aL[3], bf[0][np][2], bf[0][np][3]);
            }
        }

        if (kc == NKC - 1) {
            const int nb0 = ntp * 256 + wn0 + (lane & 3) * 2;
#pragma unroll
            for (int tn = 0; tn < 8; tn++) {
                const int n = nb0 + tn * 8;
                const float nr0 = __ldg(&g_embed_norm[n]);
                const float nr1 = __ldg(&g_embed_norm[n + 1]);
#pragma unroll
                for (int mt = 0; mt < 2; mt++) {
                    const float s0 = c[mt][tn][0] - nr0;
                    const float s1 = c[mt][tn][1] - nr1;
                    const float s2 = c[mt][tn][2] - nr0;
                    const float s3 = c[mt][tn][3] - nr1;
                    const int b0 = mt * 2, b1 = mt * 2 + 1;
                    if (s0 > bestS[b0]) { bestS[b0] = s0; bestI[b0] = n; }
                    if (s1 > bestS[b0]) { bestS[b0] = s1; bestI[b0] = n + 1; }
                    if (s2 > bestS[b1]) { bestS[b1] = s2; bestI[b1] = n; }
                    if (s3 > bestS[b1]) { bestS[b1] = s3; bestI[b1] = n + 1; }
                    c[mt][tn][0] = 0.f; c[mt][tn][1] = 0.f;
                    c[mt][tn][2] = 0.f; c[mt][tn][3] = 0.f;
                }
            }
        }
        stg = (stg + 1) % NSTG;
    }

    __syncthreads();
    float* redS = (float*)smdyn;
    int*   redI = (int*)(smdyn + 1024);

    float rs[4]; int ri[4];
#pragma unroll
    for (int r = 0; r < 4; r++) {
        float s = bestS[r]; int i = bestI[r];
#pragma unroll
        for (int off = 1; off <= 2; off <<= 1) {
            float so = __shfl_xor_sync(0xffffffffu, s, off);
            int   io = __shfl_xor_sync(0xffffffffu, i, off);
            if (so > s || (so == s && io < i)) { s = so; i = io; }
        }
        rs[r] = s; ri[r] = i;
    }
    if ((lane & 3) == 0) {
#pragma unroll
        for (int r = 0; r < 4; r++) {
            const int rl = wm0 + (r >> 1) * 16 + (r & 1) * 8 + (lane >> 2);
            redS[ncol * 64 + rl] = rs[r];
            redI[ncol * 64 + rl] = ri[r];
        }
    }
    __syncthreads();
    if (ncol == 0 && (lane & 3) == 0) {
#pragma unroll
        for (int r = 0; r < 4; r++) {
            const int rl = wm0 + (r >> 1) * 16 + (r & 1) * 8 + (lane >> 2);
            float s = redS[rl]; int i = redI[rl];
#pragma unroll
            for (int cix = 1; cix < 4; cix++) {
                const float so = redS[cix * 64 + rl];
                const int   io = redI[cix * 64 + rl];
                if (so > s || (so == s && io < i)) { s = so; i = io; }
            }
            const int slot = t0 * 64 + rl;
            if (slot < nfix) {
                const int mm = g_fix[slot];
                g_ids[mm] = i;
                const int sp = mm & 4095;
                out_ids[(mm & ~4095) | ((sp & 63) << 6) | (sp >> 6)] = (float)i;
            }
        }
    }
}

// ---------------------------------------------------------------------------
// K2: quantized write + commit-loss SSE + segment sums (proven R1 code)
// ---------------------------------------------------------------------------
__global__ __launch_bounds__(256)
void k_quant(const float* __restrict__ x, const float* __restrict__ embed,
             float* __restrict__ out_q) {
    __shared__ float qs[32][257];
    __shared__ int   sid[32];
    __shared__ float red[8];

    const int t = threadIdx.x;
    const int lane = t & 31, warp = t >> 5;
    const int m0 = blockIdx.x * 32;
    const int b = m0 >> 12;
    const int s0 = m0 & 4095;

    if (t < 32) sid[t] = g_ids[m0 + t];
    __syncthreads();
#pragma unroll
    for (int r = 0; r < 4; r++) {
        const int pp = warp + r * 8;
        const float* row = embed + sid[pp] * CC;
#pragma unroll
        for (int jj = 0; jj < 8; jj++) qs[pp][lane + 32 * jj] = row[lane + 32 * jj];
    }
    __syncthreads();

    const float* xb = x + b * (CC * HWS) + s0;
    float* qb = out_q + b * (CC * HWS) + s0;
    const int myid = sid[lane];
    float lsum = 0.f;
#pragma unroll
    for (int ci = 0; ci < 32; ci++) {
        const int cc = warp + ci * 8;
        float xv = xb[cc * HWS + lane];
        float qv = qs[lane][cc];
        qb[cc * HWS + lane] = qv;
        float dd = xv - qv;
        lsum = fmaf(dd, dd, lsum);
        atomicAdd(&g_embed_sum[cc * DD + myid], xv);
    }
    if (warp == 0) atomicAdd(&g_counts[myid], 1.0f);

#pragma unroll
    for (int o = 16; o; o >>= 1) lsum += __shfl_xor_sync(0xffffffffu, lsum, o);
    if (lane == 0) red[warp] = lsum;
    __syncthreads();
    if (t == 0) {
        float s = 0.f;
#pragma unroll
        for (int i = 0; i < 8; i++) s += red[i];
        atomicAdd(&g_sse, s);
    }
}

__global__ void k_stats(const float* __restrict__ cs, float* __restrict__ out_ncs,
                        float* __restrict__ out_loss) {
    __shared__ float red[32];
    const int t = threadIdx.x;
    const int d0 = t, d1 = t + 1024;
    float n0 = MOM * cs[d0] + OMM * g_counts[d0];
    float n1 = MOM * cs[d1] + OMM * g_counts[d1];
    out_ncs[d0] = n0;
    out_ncs[d1] = n1;
    float s = n0 + n1;
#pragma unroll
    for (int o = 16; o; o >>= 1) s += __shfl_xor_sync(0xffffffffu, s, o);
    if ((t & 31) == 0) red[t >> 5] = s;
    __syncthreads();
    if (t < 32) {
        float v = red[t];
#pragma unroll
        for (int o = 16; o; o >>= 1) v += __shfl_xor_sync(0xffffffffu, v, o);
        if (t == 0) red[0] = v;
    }
    __syncthreads();
    const float n = red[0];
    const float scale = (n + (float)DD * EPSV) / n;
    g_inv_cs[d0] = scale / (n0 + EPSV);
    g_inv_cs[d1] = scale / (n1 + EPSV);
    if (t == 0) out_loss[0] = g_sse * (1.f / 16777216.f);
}

__global__ void k_embed_out(const float* __restrict__ embed_avg,
                            float* __restrict__ out_nea, float* __restrict__ out_ne) {
    const int idx = blockIdx.x * 256 + threadIdx.x;
    const int cc = idx >> 11, d = idx & 2047;
    float nea = MOM * embed_avg[idx] + OMM * g_embed_sum[idx];
    out_nea[idx] = nea;
    out_ne[d * CC + cc] = nea * g_inv_cs[d];
}

// ---------------------------------------------------------------------------
extern "C" void kernel_launch(void* const* d_in, const int* in_sizes, int n_in,
                              void* d_out, int out_size) {
    const float* x     = (const float*)d_in[0];
    const float* embed = (const float*)d_in[1];
    const float* cs    = (const float*)d_in[2];
    const float* ea    = (const float*)d_in[3];
    float* out = (float*)d_out;

    cudaFuncSetAttribute(k_screen,  cudaFuncAttributeMaxDynamicSharedMemorySize, SMEM_SCREEN);
    cudaFuncSetAttribute(k_fix_mma, cudaFuncAttributeMaxDynamicSharedMemorySize, SMEM_FIX);

    k_zero<<<(CC * DD + DD + 2 + 255) / 256, 256>>>();
    k_norm<<<DD / 8, 256>>>(embed);
    prep_B<<<16 * NKC, 256>>>(embed);
    k_screen<<<NPIX / 64, 256, SMEM_SCREEN>>>(x, out + OFF_IDS);
    k_fix_mma<<<NPIX / 64, 256, SMEM_FIX>>>(x, out + OFF_IDS);
    k_quant<<<NPIX / 32, 256>>>(x, embed, out + OFF_Q);
    k_stats<<<1, 1024>>>(cs, out + OFF_NCS, out + OFF_LOSS);
    k_embed_out<<<(CC * DD) / 256, 256>>>(ea, out + OFF_NEA, out + OFF_NE);
}

// round 17
// speedup vs baseline: 3.4608x; 1.0535x over previous
#include <cuda_runtime.h>
#include <cuda_fp16.h>
#include <cstdint>

// Problem constants
#define BB 16
#define CC 256
#define HWS 4096
#define NPIX 65536
#define DD 2048
#define MOM 0.99f
#define OMM 0.01f
#define EPSV 1e-5f

// Output layout (float32, reference return order)
#define OFF_Q    0
#define OFF_LOSS 16777216
#define OFF_IDS  16777217
#define OFF_NE   16842753
#define OFF_NCS  17367041
#define OFF_NEA  17369089

#define NKC 16            // K chunks of 16 (K=256)
#define NTP 8             // N-tile pairs (2048 codes / 256)
#define NIT (NTP * NKC)   // 128 iterations (fix kernel)
#define NIT2 (NTP * 8)    // 64 iterations (screen: K=32 per iter)
#define NSTG 3            // cp.async pipeline stages
#define TAU 0.15f         // screen ambiguity threshold

// Screen smem (per CTA = 81920 B -> 2 CTAs/SM, reg-limited anyway)
#define SAPL_OFF 0        // A hi plane: [kc 16][oct 2][px 64] x 16B = 32768
#define SBST_OFF 32768    // B stages: 3 x 16384 = 49152
#define SMEM_SCREEN 81920

// Fix smem (per CTA = 114688 B -> 2 CTAs/SM), R10 layout
#define FAPL_OFF 0        // A planes: [kc 16][plane 2][oct 2][px 64] x 16B = 65536
#define FBST_OFF 65536    // B stages: 3 x 16384
#define SMEM_FIX 114688

// Scratch (small device globals only)
__device__ __align__(16) unsigned char g_Bpl[16u*NKC*8192u]; // [ntile][kchunk] 8KB: hi(4KB)+lo(4KB) fp16 embed planes
__device__ float g_embed_norm[DD];
__device__ int   g_ids[NPIX];
__device__ float g_counts[DD];
__device__ float g_embed_sum[CC * DD];
__device__ float g_inv_cs[DD];
__device__ float g_sse;
__device__ int   g_nfix;
__device__ int   g_fix[NPIX];

// ---------------- PTX helpers (sm_80-baseline features only) ----------------
__device__ __forceinline__ uint32_t smem_u32(const void* p) {
    uint32_t a;
    asm("{ .reg .u64 t; cvta.to.shared.u64 t, %1; cvt.u32.u64 %0, t; }" : "=r"(a) : "l"(p));
    return a;
}
#define CP16(dst, src) asm volatile("cp.async.cg.shared.global [%0], [%1], 16;" :: "r"(dst), "l"(src))
#define CP_COMMIT() asm volatile("cp.async.commit_group;" ::: "memory")
#define CP_WAIT1()  asm volatile("cp.async.wait_group 1;" ::: "memory")
#define CP_WAIT0()  asm volatile("cp.async.wait_group 0;" ::: "memory")

#define LDSM_X4(r0,r1,r2,r3,addr) \
    asm volatile("ldmatrix.sync.aligned.m8n8.x4.shared.b16 {%0,%1,%2,%3}, [%4];" \
        : "=r"(r0),"=r"(r1),"=r"(r2),"=r"(r3) : "r"(addr))
#define LDSM_X4_T(r0,r1,r2,r3,addr) \
    asm volatile("ldmatrix.sync.aligned.m8n8.x4.trans.shared.b16 {%0,%1,%2,%3}, [%4];" \
        : "=r"(r0),"=r"(r1),"=r"(r2),"=r"(r3) : "r"(addr))

#define MMA16816(c, a0,a1,a2,a3, b0,b1) \
    asm volatile("mma.sync.aligned.m16n8k16.row.col.f32.f16.f16.f32 " \
        "{%0,%1,%2,%3}, {%4,%5,%6,%7}, {%8,%9}, {%0,%1,%2,%3};" \
        : "+f"((c)[0]),"+f"((c)[1]),"+f"((c)[2]),"+f"((c)[3]) \
        : "r"(a0),"r"(a1),"r"(a2),"r"(a3),"r"(b0),"r"(b1))

// ---------------------------------------------------------------------------
__global__ void k_zero() {
    int idx = blockIdx.x * 256 + threadIdx.x;
    if (idx < CC * DD)                 g_embed_sum[idx] = 0.f;
    else if (idx < CC * DD + DD)       g_counts[idx - CC * DD] = 0.f;
    else if (idx == CC * DD + DD)      g_sse = 0.f;
    else if (idx == CC * DD + DD + 1)  g_nfix = 0;
}

__global__ void k_norm(const float* __restrict__ embed) {
    int warp = threadIdx.x >> 5, lane = threadIdx.x & 31;
    int d = blockIdx.x * 8 + warp;
    const float* row = embed + d * CC;
    float s = 0.f;
#pragma unroll
    for (int j = 0; j < 8; j++) { float v = row[lane + 32 * j]; s = fmaf(v, v, s); }
#pragma unroll
    for (int o = 16; o; o >>= 1) s += __shfl_xor_sync(0xffffffffu, s, o);
    if (lane == 0) g_embed_norm[d] = s;
}

// ---------------------------------------------------------------------------
// prep_B: embed -> fp16 hi/lo planes. Chunk (nt,kc) = 8KB: hi@0, lo@4096.
// Each plane: [k 16][swizzled 16B unit = 8 consecutive n], conflict-free ldsm.trans
// ---------------------------------------------------------------------------
__global__ __launch_bounds__(256) void prep_B(const float* __restrict__ embed) {
    const int nt = blockIdx.x / NKC, kc = blockIdx.x % NKC;
    const int t = threadIdx.x;
    const int k = t >> 4, nblk = t & 15;
    const int kglob = kc * 16 + k;
    const int n0 = nt * 128 + nblk * 8;
    uint32_t hu[4], lu[4];
#pragma unroll
    for (int nn = 0; nn < 8; nn += 2) {
        float v0 = embed[(n0 + nn) * CC + kglob];
        float v1 = embed[(n0 + nn + 1) * CC + kglob];
        __half h0 = __float2half_rn(v0), h1 = __float2half_rn(v1);
        __half l0 = __float2half_rn(v0 - __half2float(h0));
        __half l1 = __float2half_rn(v1 - __half2float(h1));
        hu[nn >> 1] = (uint32_t)__half_as_ushort(h0) | ((uint32_t)__half_as_ushort(h1) << 16);
        lu[nn >> 1] = (uint32_t)__half_as_ushort(l0) | ((uint32_t)__half_as_ushort(l1) << 16);
    }
    const int swz = (nblk & 8) | ((nblk ^ (k & 7)) & 7);
    unsigned char* ob = g_Bpl + ((size_t)(nt * NKC + kc) << 13);
    *(uint4*)(ob + k * 256 + swz * 16) = *(uint4*)hu;
    *(uint4*)(ob + 4096 + k * 256 + swz * 16) = *(uint4*)lu;
}

// ---------------------------------------------------------------------------
// k_screen: fp16-hi 1-MMA screening GEMM, K=32 per iteration (64 iters),
// top-2 argmax; flags gap < TAU.
// Stage = 16KB: [kc-sub 2][nt-half 2] x 4KB hi-plane chunks.
// ---------------------------------------------------------------------------
__global__ __launch_bounds__(256, 2) void k_screen(const float* __restrict__ x,
                                                   float* __restrict__ out_ids) {
    extern __shared__ __align__(16) unsigned char smdyn[];
    const uint32_t sbase = smem_u32(smdyn);
    const uint32_t APL = sbase + SAPL_OFF;
    const uint32_t BST = sbase + SBST_OFF;
    const int tid = threadIdx.x;
    const int lane = tid & 31, wid = tid >> 5;
    const int wm0 = (wid >> 2) * 32;
    const int ncol = wid & 3;
    const int wn0 = ncol * 64;
    const int mblk = blockIdx.x;

#define ISSUE_S2(stg_, idx2) do { \
        const int ntp_ = (idx2) >> 3, kp_ = (idx2) & 7; \
        uint32_t db = BST + (stg_) * 16384 + tid * 16; \
        const unsigned char* c00 = g_Bpl + ((size_t)((ntp_ * 2 + 0) * NKC + kp_ * 2 + 0) << 13) + tid * 16; \
        const unsigned char* c01 = g_Bpl + ((size_t)((ntp_ * 2 + 1) * NKC + kp_ * 2 + 0) << 13) + tid * 16; \
        const unsigned char* c10 = g_Bpl + ((size_t)((ntp_ * 2 + 0) * NKC + kp_ * 2 + 1) << 13) + tid * 16; \
        const unsigned char* c11 = g_Bpl + ((size_t)((ntp_ * 2 + 1) * NKC + kp_ * 2 + 1) << 13) + tid * 16; \
        CP16(db,         c00); \
        CP16(db + 4096,  c01); \
        CP16(db + 8192,  c10); \
        CP16(db + 12288, c11); \
        CP_COMMIT(); \
    } while (0)

    ISSUE_S2(0, 0);
    ISSUE_S2(1, 1);

    // ---- Phase 1: convert A once (2x-scaled HI fp16 plane) ----
    {
        const int p = tid & 63;
        const int q = tid >> 6;
        const int m = mblk * 64 + p;
        const float* xs = x + (m >> 12) * (CC * HWS) + (m & 4095);
#pragma unroll
        for (int base = 0; base < NKC; base += 2) {
            const int kc = base + (q >> 1);
            const int oct = q & 1;
            uint32_t hu[4];
#pragma unroll
            for (int kk = 0; kk < 8; kk += 2) {
                const int ka = kc * 16 + oct * 8 + kk;
                __half h0 = __float2half_rn(2.f * xs[(size_t)ka * HWS]);
                __half h1 = __float2half_rn(2.f * xs[(size_t)(ka + 1) * HWS]);
                hu[kk >> 1] = (uint32_t)__half_as_ushort(h0) | ((uint32_t)__half_as_ushort(h1) << 16);
            }
            *(uint4*)(smdyn + SAPL_OFF + kc * 2048 + oct * 1024 + p * 16) = *(uint4*)hu;
        }
    }

    float c[2][8][4];
#pragma unroll
    for (int a = 0; a < 2; a++)
#pragma unroll
        for (int b = 0; b < 8; b++)
#pragma unroll
            for (int r = 0; r < 4; r++) c[a][b][r] = 0.f;
    float bS1[4], bS2[4];
    int   bI1[4];
#pragma unroll
    for (int r = 0; r < 4; r++) { bS1[r] = -3.4e38f; bS2[r] = -3.4e38f; bI1[r] = 0; }

    const int g = lane >> 3;
    const int kk2 = ((g & 1) << 3) | (lane & 7);
    const int nbg = g >> 1;
    const int h = wn0 >> 7;
    const int ln0 = wn0 & 127;

    int stg = 0;
    for (int ii = 0; ii < NIT2; ii++) {
        const int ntp = ii >> 3, kp = ii & 7;
        if (ii + 1 < NIT2) CP_WAIT1(); else CP_WAIT0();
        __syncthreads();
        if (ii + 2 < NIT2) ISSUE_S2((stg + 2) % NSTG, ii + 2);

#pragma unroll
        for (int sub = 0; sub < 2; sub++) {
            const int kc = kp * 2 + sub;
            const uint32_t sB = BST + stg * 16384 + sub * 8192 + h * 4096;

            uint32_t bf[4][4];
#pragma unroll
            for (int np = 0; np < 4; np++) {
                const int nblk = ((ln0 + np * 16) >> 3) + nbg;
                const uint32_t addr = sB + kk2 * 256 +
                    (((nblk & 8) | ((nblk ^ (kk2 & 7)) & 7)) << 4);
                LDSM_X4_T(bf[np][0], bf[np][1], bf[np][2], bf[np][3], addr);
            }
#pragma unroll
            for (int mt = 0; mt < 2; mt++) {
                const int mrow = wm0 + mt * 16 + (g & 1) * 8 + (lane & 7);
                uint32_t aH[4];
                const uint32_t aaddr = APL + kc * 2048 + (g >> 1) * 1024 + mrow * 16;
                LDSM_X4(aH[0], aH[1], aH[2], aH[3], aaddr);
#pragma unroll
                for (int np = 0; np < 4; np++) {
                    MMA16816(c[mt][2*np],   aH[0],aH[1],aH[2],aH[3], bf[np][0], bf[np][1]);
                    MMA16816(c[mt][2*np+1], aH[0],aH[1],aH[2],aH[3], bf[np][2], bf[np][3]);
                }
            }
        }

        if (kp == 7) {
            const int nb0 = ntp * 256 + wn0 + (lane & 3) * 2;
#pragma unroll
            for (int tn = 0; tn < 8; tn++) {
                const int n = nb0 + tn * 8;
                const float nr0 = __ldg(&g_embed_norm[n]);
                const float nr1 = __ldg(&g_embed_norm[n + 1]);
#pragma unroll
                for (int mt = 0; mt < 2; mt++) {
                    const int b0 = mt * 2, b1 = mt * 2 + 1;
                    const float s0 = c[mt][tn][0] - nr0;
                    const float s1 = c[mt][tn][1] - nr1;
                    const float s2 = c[mt][tn][2] - nr0;
                    const float s3 = c[mt][tn][3] - nr1;
                    if (s0 > bS1[b0]) { bS2[b0] = bS1[b0]; bS1[b0] = s0; bI1[b0] = n; }
                    else if (s0 > bS2[b0]) bS2[b0] = s0;
                    if (s1 > bS1[b0]) { bS2[b0] = bS1[b0]; bS1[b0] = s1; bI1[b0] = n + 1; }
                    else if (s1 > bS2[b0]) bS2[b0] = s1;
                    if (s2 > bS1[b1]) { bS2[b1] = bS1[b1]; bS1[b1] = s2; bI1[b1] = n; }
                    else if (s2 > bS2[b1]) bS2[b1] = s2;
                    if (s3 > bS1[b1]) { bS2[b1] = bS1[b1]; bS1[b1] = s3; bI1[b1] = n + 1; }
                    else if (s3 > bS2[b1]) bS2[b1] = s3;
                    c[mt][tn][0] = 0.f; c[mt][tn][1] = 0.f;
                    c[mt][tn][2] = 0.f; c[mt][tn][3] = 0.f;
                }
            }
        }
        stg = (stg + 1) % NSTG;
    }

    __syncthreads();
    float* redS1 = (float*)smdyn;
    int*   redI1 = (int*)(smdyn + 1024);
    float* redS2 = (float*)(smdyn + 2048);

    float rs1[4], rs2[4]; int ri1[4];
#pragma unroll
    for (int r = 0; r < 4; r++) {
        float s1 = bS1[r], s2 = bS2[r]; int i1 = bI1[r];
#pragma unroll
        for (int off = 1; off <= 2; off <<= 1) {
            float os1 = __shfl_xor_sync(0xffffffffu, s1, off);
            int   oi1 = __shfl_xor_sync(0xffffffffu, i1, off);
            float os2 = __shfl_xor_sync(0xffffffffu, s2, off);
            if (os1 > s1 || (os1 == s1 && oi1 < i1)) {
                s2 = fmaxf(s1, os2); s1 = os1; i1 = oi1;
            } else {
                s2 = fmaxf(s2, os1);
            }
        }
        rs1[r] = s1; rs2[r] = s2; ri1[r] = i1;
    }
    if ((lane & 3) == 0) {
#pragma unroll
        for (int r = 0; r < 4; r++) {
            const int rl = wm0 + (r >> 1) * 16 + (r & 1) * 8 + (lane >> 2);
            redS1[ncol * 64 + rl] = rs1[r];
            redI1[ncol * 64 + rl] = ri1[r];
            redS2[ncol * 64 + rl] = rs2[r];
        }
    }
    __syncthreads();
    if (ncol == 0 && (lane & 3) == 0) {
#pragma unroll
        for (int r = 0; r < 4; r++) {
            const int rl = wm0 + (r >> 1) * 16 + (r & 1) * 8 + (lane >> 2);
            float s1 = redS1[rl], s2 = redS2[rl]; int i1 = redI1[rl];
#pragma unroll
            for (int cix = 1; cix < 4; cix++) {
                const float os1 = redS1[cix * 64 + rl];
                const int   oi1 = redI1[cix * 64 + rl];
                const float os2 = redS2[cix * 64 + rl];
                if (os1 > s1 || (os1 == s1 && oi1 < i1)) {
                    s2 = fmaxf(s1, os2); s1 = os1; i1 = oi1;
                } else {
                    s2 = fmaxf(s2, os1);
                }
            }
            const int mm = mblk * 64 + rl;
            g_ids[mm] = i1;
            const int sp = mm & 4095;
            out_ids[(mm & ~4095) | ((sp & 63) << 6) | (sp >> 6)] = (float)i1;
            if (s1 - s2 < TAU) {
                const int pos = atomicAdd(&g_nfix, 1);
                g_fix[pos] = mm;
            }
        }
    }
}

// ---------------------------------------------------------------------------
// k_fix_mma: exact 3xFP16 rescore of flagged pixels (R10 mainloop, gathered A).
// ---------------------------------------------------------------------------
__global__ __launch_bounds__(256, 2) void k_fix_mma(const float* __restrict__ x,
                                                    float* __restrict__ out_ids) {
    const int nfix = g_nfix;
    const int t0 = blockIdx.x;
    if (t0 * 64 >= nfix) return;

    extern __shared__ __align__(16) unsigned char smdyn[];
    const uint32_t sbase = smem_u32(smdyn);
    const uint32_t APL = sbase + FAPL_OFF;
    const uint32_t BST = sbase + FBST_OFF;
    const int tid = threadIdx.x;
    const int lane = tid & 31, wid = tid >> 5;
    const int wm0 = (wid >> 2) * 32;
    const int ncol = wid & 3;
    const int wn0 = ncol * 64;

#define ISSUE_F(stg_, idx2) do { \
        const int ntp_ = (idx2) / NKC, kc_ = (idx2) % NKC; \
        uint32_t db = BST + (stg_) * 16384 + tid * 16; \
        const unsigned char* s0 = g_Bpl + ((size_t)((ntp_ * 2 + 0) * NKC + kc_) << 13) + tid * 16; \
        const unsigned char* s1 = g_Bpl + ((size_t)((ntp_ * 2 + 1) * NKC + kc_) << 13) + tid * 16; \
        CP16(db,          s0); \
        CP16(db + 4096,   s0 + 4096); \
        CP16(db + 8192,   s1); \
        CP16(db + 12288,  s1 + 4096); \
        CP_COMMIT(); \
    } while (0)

    ISSUE_F(0, 0);
    ISSUE_F(1, 1);

    // ---- Phase 1: convert gathered A (2x-scaled hi/lo fp16 planes) ----
    {
        const int p = tid & 63;
        const int q = tid >> 6;
        const int slot = t0 * 64 + p;
        const int m = g_fix[slot < nfix ? slot : nfix - 1];
        const float* xs = x + (m >> 12) * (CC * HWS) + (m & 4095);
#pragma unroll
        for (int base = 0; base < NKC; base += 2) {
            const int kc = base + (q >> 1);
            const int oct = q & 1;
            uint32_t hu[4], lu[4];
#pragma unroll
            for (int kk = 0; kk < 8; kk += 2) {
                const int ka = kc * 16 + oct * 8 + kk;
                float v0 = 2.f * xs[(size_t)ka * HWS];
                float v1 = 2.f * xs[(size_t)(ka + 1) * HWS];
                __half h0 = __float2half_rn(v0), h1 = __float2half_rn(v1);
                __half l0 = __float2half_rn(v0 - __half2float(h0));
                __half l1 = __float2half_rn(v1 - __half2float(h1));
                hu[kk >> 1] = (uint32_t)__half_as_ushort(h0) | ((uint32_t)__half_as_ushort(h1) << 16);
                lu[kk >> 1] = (uint32_t)__half_as_ushort(l0) | ((uint32_t)__half_as_ushort(l1) << 16);
            }
            *(uint4*)(smdyn + FAPL_OFF + kc * 4096 + oct * 1024 + p * 16)        = *(uint4*)hu;
            *(uint4*)(smdyn + FAPL_OFF + kc * 4096 + 2048 + oct * 1024 + p * 16) = *(uint4*)lu;
        }
    }

    float c[2][8][4];
#pragma unroll
    for (int a = 0; a < 2; a++)
#pragma unroll
        for (int b = 0; b < 8; b++)
#pragma unroll
            for (int r = 0; r < 4; r++) c[a][b][r] = 0.f;
    float bestS[4];
    int   bestI[4];
#pragma unroll
    for (int r = 0; r < 4; r++) { bestS[r] = -3.4e38f; bestI[r] = 0; }

    const int g = lane >> 3;
    const int kk2 = ((g & 1) << 3) | (lane & 7);
    const int nbg = g >> 1;
    const int h = wn0 >> 7;
    const int ln0 = wn0 & 127;

    int stg = 0;
    for (int ii = 0; ii < NIT; ii++) {
        const int ntp = ii / NKC, kc = ii % NKC;
        if (ii + 1 < NIT) CP_WAIT1(); else CP_WAIT0();
        __syncthreads();
        if (ii + 2 < NIT) ISSUE_F((stg + 2) % NSTG, ii + 2);

        const uint32_t sB = BST + stg * 16384 + h * 8192;

        uint32_t bf[2][4][4];
#pragma unroll
        for (int pp = 0; pp < 2; pp++)
#pragma unroll
            for (int np = 0; np < 4; np++) {
                const int nblk = ((ln0 + np * 16) >> 3) + nbg;
                const uint32_t addr = sB + pp * 4096 + kk2 * 256 +
                    (((nblk & 8) | ((nblk ^ (kk2 & 7)) & 7)) << 4);
                LDSM_X4_T(bf[pp][np][0], bf[pp][np][1], bf[pp][np][2], bf[pp][np][3], addr);
            }
#pragma unroll
        for (int mt = 0; mt < 2; mt++) {
            const int mrow = wm0 + mt * 16 + (g & 1) * 8 + (lane & 7);
            uint32_t aH[4], aL[4];
            const uint32_t aaddr = APL + kc * 4096 + (g >> 1) * 1024 + mrow * 16;
            LDSM_X4(aH[0], aH[1], aH[2], aH[3], aaddr);
            LDSM_X4(aL[0], aL[1], aL[2], aL[3], aaddr + 2048);
#pragma unroll
            for (int np = 0; np < 4; np++) {
                MMA16816(c[mt][2*np],   aH[0],aH[1],aH[2],aH[3], bf[0][np][0], bf[0][np][1]);
                MMA16816(c[mt][2*np],   aH[0],aH[1],aH[2],aH[3], bf[1][np][0], bf[1][np][1]);
                MMA16816(c[mt][2*np],   aL[0],aL[1],aL[2],aL[3], bf[0][np][0], bf[0][np][1]);
                MMA16816(c[mt][2*np+1], aH[0],aH[1],aH[2],aH[3], bf[0][np][2], bf[0][np][3]);
                MMA16816(c[mt][2*np+1], aH[0],aH[1],aH[2],aH[3], bf[1][np][2], bf[1][np][3]);
                MMA16816(c[mt][2*np+1], aL[0],aL[1],aL[2],aL[3], bf[0][np][2], bf[0][np][3]);
            }
        }

        if (kc == NKC - 1) {
            const int nb0 = ntp * 256 + wn0 + (lane & 3) * 2;
#pragma unroll
            for (int tn = 0; tn < 8; tn++) {
                const int n = nb0 + tn * 8;
                const float nr0 = __ldg(&g_embed_norm[n]);
                const float nr1 = __ldg(&g_embed_norm[n + 1]);
#pragma unroll
                for (int mt = 0; mt < 2; mt++) {
                    const float s0 = c[mt][tn][0] - nr0;
                    const float s1 = c[mt][tn][1] - nr1;
                    const float s2 = c[mt][tn][2] - nr0;
                    const float s3 = c[mt][tn][3] - nr1;
                    const int b0 = mt * 2, b1 = mt * 2 + 1;
                    if (s0 > bestS[b0]) { bestS[b0] = s0; bestI[b0] = n; }
                    if (s1 > bestS[b0]) { bestS[b0] = s1; bestI[b0] = n + 1; }
                    if (s2 > bestS[b1]) { bestS[b1] = s2; bestI[b1] = n; }
                    if (s3 > bestS[b1]) { bestS[b1] = s3; bestI[b1] = n + 1; }
                    c[mt][tn][0] = 0.f; c[mt][tn][1] = 0.f;
                    c[mt][tn][2] = 0.f; c[mt][tn][3] = 0.f;
                }
            }
        }
        stg = (stg + 1) % NSTG;
    }

    __syncthreads();
    float* redS = (float*)smdyn;
    int*   redI = (int*)(smdyn + 1024);

    float rs[4]; int ri[4];
#pragma unroll
    for (int r = 0; r < 4; r++) {
        float s = bestS[r]; int i = bestI[r];
#pragma unroll
        for (int off = 1; off <= 2; off <<= 1) {
            float so = __shfl_xor_sync(0xffffffffu, s, off);
            int   io = __shfl_xor_sync(0xffffffffu, i, off);
            if (so > s || (so == s && io < i)) { s = so; i = io; }
        }
        rs[r] = s; ri[r] = i;
    }
    if ((lane & 3) == 0) {
#pragma unroll
        for (int r = 0; r < 4; r++) {
            const int rl = wm0 + (r >> 1) * 16 + (r & 1) * 8 + (lane >> 2);
            redS[ncol * 64 + rl] = rs[r];
            redI[ncol * 64 + rl] = ri[r];
        }
    }
    __syncthreads();
    if (ncol == 0 && (lane & 3) == 0) {
#pragma unroll
        for (int r = 0; r < 4; r++) {
            const int rl = wm0 + (r >> 1) * 16 + (r & 1) * 8 + (lane >> 2);
            float s = redS[rl]; int i = redI[rl];
#pragma unroll
            for (int cix = 1; cix < 4; cix++) {
                const float so = redS[cix * 64 + rl];
                const int   io = redI[cix * 64 + rl];
                if (so > s || (so == s && io < i)) { s = so; i = io; }
            }
            const int slot = t0 * 64 + rl;
            if (slot < nfix) {
                const int mm = g_fix[slot];
                g_ids[mm] = i;
                const int sp = mm & 4095;
                out_ids[(mm & ~4095) | ((sp & 63) << 6) | (sp >> 6)] = (float)i;
            }
        }
    }
}

// ---------------------------------------------------------------------------
// K2: quantized write + commit-loss SSE + segment sums (proven R1 code)
// ---------------------------------------------------------------------------
__global__ __launch_bounds__(256)
void k_quant(const float* __restrict__ x, const float* __restrict__ embed,
             float* __restrict__ out_q) {
    __shared__ float qs[32][257];
    __shared__ int   sid[32];
    __shared__ float red[8];

    const int t = threadIdx.x;
    const int lane = t & 31, warp = t >> 5;
    const int m0 = blockIdx.x * 32;
    const int b = m0 >> 12;
    const int s0 = m0 & 4095;

    if (t < 32) sid[t] = g_ids[m0 + t];
    __syncthreads();
#pragma unroll
    for (int r = 0; r < 4; r++) {
        const int pp = warp + r * 8;
        const float* row = embed + sid[pp] * CC;
#pragma unroll
        for (int jj = 0; jj < 8; jj++) qs[pp][lane + 32 * jj] = row[lane + 32 * jj];
    }
    __syncthreads();

    const float* xb = x + b * (CC * HWS) + s0;
    float* qb = out_q + b * (CC * HWS) + s0;
    const int myid = sid[lane];
    float lsum = 0.f;
#pragma unroll
    for (int ci = 0; ci < 32; ci++) {
        const int cc = warp + ci * 8;
        float xv = xb[cc * HWS + lane];
        float qv = qs[lane][cc];
        qb[cc * HWS + lane] = qv;
        float dd = xv - qv;
        lsum = fmaf(dd, dd, lsum);
        atomicAdd(&g_embed_sum[cc * DD + myid], xv);
    }
    if (warp == 0) atomicAdd(&g_counts[myid], 1.0f);

#pragma unroll
    for (int o = 16; o; o >>= 1) lsum += __shfl_xor_sync(0xffffffffu, lsum, o);
    if (lane == 0) red[warp] = lsum;
    __syncthreads();
    if (t == 0) {
        float s = 0.f;
#pragma unroll
        for (int i = 0; i < 8; i++) s += red[i];
        atomicAdd(&g_sse, s);
    }
}

__global__ void k_stats(const float* __restrict__ cs, float* __restrict__ out_ncs,
                        float* __restrict__ out_loss) {
    __shared__ float red[32];
    const int t = threadIdx.x;
    const int d0 = t, d1 = t + 1024;
    float n0 = MOM * cs[d0] + OMM * g_counts[d0];
    float n1 = MOM * cs[d1] + OMM * g_counts[d1];
    out_ncs[d0] = n0;
    out_ncs[d1] = n1;
    float s = n0 + n1;
#pragma unroll
    for (int o = 16; o; o >>= 1) s += __shfl_xor_sync(0xffffffffu, s, o);
    if ((t & 31) == 0) red[t >> 5] = s;
    __syncthreads();
    if (t < 32) {
        float v = red[t];
#pragma unroll
        for (int o = 16; o; o >>= 1) v += __shfl_xor_sync(0xffffffffu, v, o);
        if (t == 0) red[0] = v;
    }
    __syncthreads();
    const float n = red[0];
    const float scale = (n + (float)DD * EPSV) / n;
    g_inv_cs[d0] = scale / (n0 + EPSV);
    g_inv_cs[d1] = scale / (n1 + EPSV);
    if (t == 0) out_loss[0] = g_sse * (1.f / 16777216.f);
}

__global__ void k_embed_out(const float* __restrict__ embed_avg,
                            float* __restrict__ out_nea, float* __restrict__ out_ne) {
    const int idx = blockIdx.x * 256 + threadIdx.x;
    const int cc = idx >> 11, d = idx & 2047;
    float nea = MOM * embed_avg[idx] + OMM * g_embed_sum[idx];
    out_nea[idx] = nea;
    out_ne[d * CC + cc] = nea * g_inv_cs[d];
}

// ---------------------------------------------------------------------------
extern "C" void kernel_launch(void* const* d_in, const int* in_sizes, int n_in,
                              void* d_out, int out_size) {
    const float* x     = (const float*)d_in[0];
    const float* embed = (const float*)d_in[1];
    const float* cs    = (const float*)d_in[2];
    const float* ea    = (const float*)d_in[3];
    float* out = (float*)d_out;

    cudaFuncSetAttribute(k_screen,  cudaFuncAttributeMaxDynamicSharedMemorySize, SMEM_SCREEN);
    cudaFuncSetAttribute(k_fix_mma, cudaFuncAttributeMaxDynamicSharedMemorySize, SMEM_FIX);

    k_zero<<<(CC * DD + DD + 2 + 255) / 256, 256>>>();
    k_norm<<<DD / 8, 256>>>(embed);
    prep_B<<<16 * NKC, 256>>>(embed);
    k_screen<<<NPIX / 64, 256, SMEM_SCREEN>>>(x, out + OFF_IDS);
    k_fix_mma<<<NPIX / 64, 256, SMEM_FIX>>>(x, out + OFF_IDS);
    k_quant<<<NPIX / 32, 256>>>(x, embed, out + OFF_Q);
    k_stats<<<1, 1024>>>(cs, out + OFF_NCS, out + OFF_LOSS);
    k_embed_out<<<(CC * DD) / 256, 256>>>(ea, out + OFF_NEA, out + OFF_NE);
}